// round 11
// baseline (speedup 1.0000x reference)
#include <cuda_runtime.h>
#include <cuda_fp16.h>
#include <stdint.h>
#include <math.h>

#define NB 128
#define NI 1152
#define IC 16                   // i per k_hat CTA
#define ICHUNKS (NI/IC)         // 72
#define BC 16                   // b per k_hat CTA (8 pairs)
#define CL 4                    // cluster size (CTAs per batch)
#define IPC (NI/CL)             // 288 i per route CTA
#define RSLOTS 16               // 8 warps x 2 i-slots
#define RSTEPS (IPC/RSLOTS)     // 18

// Dynamic smem layout for k_route (bytes)
#define OFF_HAT  0
#define HAT_BYTES (IPC*512)               // 147456
#define OFF_RED  HAT_BYTES                // 16*256*4 = 16384
#define OFF_P1   (OFF_RED + 16384)        // 1024
#define OFF_P2   (OFF_P1 + 1024)
#define OFF_OUT0 (OFF_P2 + 1024)
#define OFF_VEC  (OFF_OUT0 + 1024)
#define RSMEM    (OFF_VEC + 1024)         // 167936

// Scratch (static device globals; no runtime allocation)
__device__ __half g_hat[(size_t)NB * NI * 256];   // [b][i][n*16+e], 75.5 MB
__device__ float  g_s0p[(size_t)ICHUNKS * NB * 256];

// ---- packed f32x2 helpers (Blackwell FFMA2 via PTX) ----
__device__ __forceinline__ uint64_t pk(float a, float b) {
    uint64_t r; asm("mov.b64 %0, {%1,%2};" : "=l"(r) : "f"(a), "f"(b)); return r;
}
__device__ __forceinline__ void unpk(uint64_t v, float& lo, float& hi) {
    asm("mov.b64 {%0,%1}, %2;" : "=f"(lo), "=f"(hi) : "l"(v));
}
__device__ __forceinline__ uint64_t mul2(uint64_t a, uint64_t b) {
    uint64_t r; asm("mul.rn.f32x2 %0, %1, %2;" : "=l"(r) : "l"(a), "l"(b)); return r;
}
__device__ __forceinline__ void fma2(uint64_t& d, uint64_t a, uint64_t b) {
    asm("fma.rn.f32x2 %0, %1, %2, %3;" : "=l"(d) : "l"(a), "l"(b), "l"(d));
}
__device__ __forceinline__ void add2(uint64_t& d, uint64_t a) {
    asm("add.rn.f32x2 %0, %1, %2;" : "=l"(d) : "l"(a), "l"(d));
}

// ---- cluster helpers ----
__device__ __forceinline__ uint32_t smem_u32(const void* p) {
    uint32_t a;
    asm("{ .reg .u64 t; cvta.to.shared.u64 t, %1; cvt.u32.u64 %0, t; }"
        : "=r"(a) : "l"(p));
    return a;
}
__device__ __forceinline__ uint32_t mapa_u32(uint32_t saddr, uint32_t rank) {
    uint32_t r;
    asm("mapa.shared::cluster.u32 %0, %1, %2;" : "=r"(r) : "r"(saddr), "r"(rank));
    return r;
}
__device__ __forceinline__ float ld_dsmem(uint32_t addr) {
    float v;
    asm volatile("ld.shared::cluster.f32 %0, [%1];" : "=f"(v) : "r"(addr));
    return v;
}
#define CLUSTER_SYNC() do { \
    asm volatile("barrier.cluster.arrive.aligned;" ::: "memory"); \
    asm volatile("barrier.cluster.wait.aligned;" ::: "memory"); \
} while (0)

// ---------------------------------------------------------------------------
// k_hat (R8-measured-best): hat[b,i,n,e] = sum_d x[b,i,d]*W[n,i,e,d], fp16.
// grid (72, 8), 256 threads: t = n*16 + e. Batch pairs via packed f32x2.
// ---------------------------------------------------------------------------
__global__ void __launch_bounds__(256) k_hat(const float* __restrict__ x,
                                             const float* __restrict__ W) {
    __shared__ uint64_t sxp[8][IC][8];   // (x_b, x_b+1) pairs, 8KB
    const int t  = threadIdx.x;
    const int i0 = blockIdx.x * IC;
    const int b0 = blockIdx.y * BC;

    for (int idx = t; idx < 8 * IC * 8; idx += 256) {
        int b2 = idx >> 7, rem = idx & 127;
        int ii = rem >> 3, d = rem & 7;
        float va = x[((size_t)(b0 + 2*b2    ) * NI + i0 + ii) * 8 + d];
        float vb = x[((size_t)(b0 + 2*b2 + 1) * NI + i0 + ii) * 8 + d];
        sxp[b2][ii][d] = pk(va, vb);
    }
    __syncthreads();

    const float4* wp = reinterpret_cast<const float4*>(W)
                     + ((size_t)((t >> 4) * NI + i0) * 16 + (t & 15)) * 2;

    uint64_t s0[8];
#pragma unroll
    for (int k = 0; k < 8; ++k) s0[k] = 0ull;

    float4 wa = wp[0], wb = wp[1];
    for (int i = 0; i < IC; ++i) {
        float4 na, nb;
        if (i + 1 < IC) { na = wp[32]; nb = wp[33]; }
        wp += 32;

        uint64_t ws[8];
        ws[0] = pk(wa.x, wa.x); ws[1] = pk(wa.y, wa.y);
        ws[2] = pk(wa.z, wa.z); ws[3] = pk(wa.w, wa.w);
        ws[4] = pk(wb.x, wb.x); ws[5] = pk(wb.y, wb.y);
        ws[6] = pk(wb.z, wb.z); ws[7] = pk(wb.w, wb.w);

#pragma unroll
        for (int b2 = 0; b2 < 8; ++b2) {
            const ulonglong2* xp2 = reinterpret_cast<const ulonglong2*>(&sxp[b2][i][0]);
            ulonglong2 q0 = xp2[0], q1 = xp2[1];
            ulonglong2 q2 = xp2[2], q3 = xp2[3];
            uint64_t acc = mul2(ws[0], q0.x);
            fma2(acc, ws[1], q0.y);
            fma2(acc, ws[2], q1.x);
            fma2(acc, ws[3], q1.y);
            fma2(acc, ws[4], q2.x);
            fma2(acc, ws[5], q2.y);
            fma2(acc, ws[6], q3.x);
            fma2(acc, ws[7], q3.y);
            add2(s0[b2], acc);
            float lo, hi; unpk(acc, lo, hi);
            size_t base = ((size_t)(b0 + 2*b2) * NI + i0 + i) * 256 + t;
            g_hat[base]                    = __float2half_rn(lo);
            g_hat[base + (size_t)NI * 256] = __float2half_rn(hi);
        }
        wa = na; wb = nb;
    }
#pragma unroll
    for (int b2 = 0; b2 < 8; ++b2) {
        float lo, hi; unpk(s0[b2], lo, hi);
        g_s0p[((size_t)blockIdx.x * NB + b0 + 2*b2    ) * 256 + t] = lo;
        g_s0p[((size_t)blockIdx.x * NB + b0 + 2*b2 + 1) * 256 + t] = hi;
    }
}

// squash along e via warp butterfly over low 4 lane bits (t = n*16+e)
__device__ __forceinline__ float squash_val(float sv) {
    float sq = sv * sv;
    sq += __shfl_xor_sync(0xffffffffu, sq, 1);
    sq += __shfl_xor_sync(0xffffffffu, sq, 2);
    sq += __shfl_xor_sync(0xffffffffu, sq, 4);
    sq += __shfl_xor_sync(0xffffffffu, sq, 8);
    float scale = sq / ((1.f + sq) * sqrtf(sq));
    return sv * scale;
}

// One i: fp16 hat fragment -> logit dot (packed), softmax over n (4 shfl),
// packed-fma accumulate into sacc.
__device__ __forceinline__ void step_i(uint4 A0, uint4 A1,
                                       const uint64_t vecp[8], uint64_t sacc[8]) {
    uint64_t fp[8];
    const __half2* ha = reinterpret_cast<const __half2*>(&A0);
#pragma unroll
    for (int j = 0; j < 4; ++j) { float2 v = __half22float2(ha[j]); fp[j] = pk(v.x, v.y); }
    const __half2* hb = reinterpret_cast<const __half2*>(&A1);
#pragma unroll
    for (int j = 0; j < 4; ++j) { float2 v = __half22float2(hb[j]); fp[4+j] = pk(v.x, v.y); }

    uint64_t dacc = mul2(vecp[0], fp[0]);
#pragma unroll
    for (int j = 1; j < 8; ++j) fma2(dacc, vecp[j], fp[j]);
    float dlo, dhi; unpk(dacc, dlo, dhi);
    float E = __expf(dlo + dhi);
    float den = E;
    den += __shfl_xor_sync(0xffffffffu, den, 1);
    den += __shfl_xor_sync(0xffffffffu, den, 2);
    den += __shfl_xor_sync(0xffffffffu, den, 4);
    den += __shfl_xor_sync(0xffffffffu, den, 8);
    float c = __fdividef(E, den);
    uint64_t cp = pk(c, c);
#pragma unroll
    for (int j = 0; j < 8; ++j) fma2(sacc[j], cp, fp[j]);
}

// Sweep this CTA's 288-i smem tile. Swizzle: byte ^= (i&1)<<4 makes the
// n-strided reads conflict-free (verified: 4 lanes per bank-quad/wavefront).
__device__ __forceinline__ void sweep_smem(const char* sm, const uint64_t vecp[8],
                                           int n, int slot, float* sRed) {
    uint64_t sacc[8];
#pragma unroll
    for (int j = 0; j < 8; ++j) sacc[j] = 0ull;

#pragma unroll 2
    for (int s = 0; s < RSTEPS; ++s) {
        int i = s * RSLOTS + slot;
        uint32_t a = (uint32_t)i * 512 + (uint32_t)n * 32;
        uint32_t sw = (uint32_t)(i & 1) << 4;
        uint4 A0 = *reinterpret_cast<const uint4*>(sm + (a ^ sw));
        uint4 A1 = *reinterpret_cast<const uint4*>(sm + ((a + 16) ^ sw));
        step_i(A0, A1, vecp, sacc);
    }
#pragma unroll
    for (int j = 0; j < 8; ++j) {
        float lo, hi; unpk(sacc[j], lo, hi);
        sRed[slot * 256 + n * 16 + 2*j]     = lo;
        sRed[slot * 256 + n * 16 + 2*j + 1] = hi;
    }
}

// ---------------------------------------------------------------------------
// k_route: 4-CTA cluster per batch. Each CTA stages 288 i of hat into smem
// ONCE; both passes read smem. Cross-CTA partials exchanged via DSMEM +
// cluster.sync (HW-guaranteed co-residency). grid (4, 128), 256 threads.
// ---------------------------------------------------------------------------
__global__ void __launch_bounds__(256) __cluster_dims__(CL, 1, 1)
k_route(const float* __restrict__ Bias, float* __restrict__ out) {
    extern __shared__ char sm[];
    float* sRed  = reinterpret_cast<float*>(sm + OFF_RED);
    float* sP1   = reinterpret_cast<float*>(sm + OFF_P1);
    float* sP2   = reinterpret_cast<float*>(sm + OFF_P2);
    float* sOut0 = reinterpret_cast<float*>(sm + OFF_OUT0);
    float* sVec  = reinterpret_cast<float*>(sm + OFF_VEC);

    const int rank = blockIdx.x, b = blockIdx.y;
    const int t = threadIdx.x, warp = t >> 5, lane = t & 31;
    const int n = lane & 15, islot = lane >> 4;
    const int slot = warp * 2 + islot;
    const float bias = Bias[t];

    // ---- stage hat slice gmem -> smem (contiguous, swizzled dst) ----
    {
        const uint4* src = reinterpret_cast<const uint4*>(
            g_hat + ((size_t)b * NI + rank * IPC) * 256);
#pragma unroll 4
        for (int j = t; j < HAT_BYTES / 16; j += 256) {
            uint4 v = src[j];
            uint32_t o = (uint32_t)j * 16;
            uint32_t od = o ^ (((o >> 9) & 1) << 4);
            *reinterpret_cast<uint4*>(sm + od) = v;
        }
    }

    // ---- head: out0 = squash(sum_i hat /16 + Bias) (redundant per CTA) ----
    {
        float sv = 0.f;
        for (int c = 0; c < ICHUNKS; ++c)
            sv += g_s0p[((size_t)c * NB + b) * 256 + t];
        sv = sv * (1.f / 16.f) + bias;
        float o = squash_val(sv);
        sOut0[t] = o; sVec[t] = o;
    }
    __syncthreads();

    uint64_t vecp[8];
#pragma unroll
    for (int j = 0; j < 8; ++j)
        vecp[j] = pk(sVec[n * 16 + 2*j], sVec[n * 16 + 2*j + 1]);

    // ---- pass 1 (smem) ----
    sweep_smem(sm, vecp, n, slot, sRed);
    __syncthreads();
    {
        float sv = 0.f;
#pragma unroll
        for (int w = 0; w < RSLOTS; ++w) sv += sRed[w * 256 + t];
        sP1[t] = sv;
    }
    __syncthreads();
    CLUSTER_SYNC();

    // gather 4 rank partials via DSMEM -> out1 -> telescoped vec
    {
        uint32_t myP1 = smem_u32(sP1 + t);
        float s1 = 0.f;
#pragma unroll
        for (uint32_t r = 0; r < CL; ++r) s1 += ld_dsmem(mapa_u32(myP1, r));
        s1 += bias;
        sVec[t] = sOut0[t] + squash_val(s1);
    }
    __syncthreads();

#pragma unroll
    for (int j = 0; j < 8; ++j)
        vecp[j] = pk(sVec[n * 16 + 2*j], sVec[n * 16 + 2*j + 1]);

    // ---- pass 2 (smem) ----
    sweep_smem(sm, vecp, n, slot, sRed);
    __syncthreads();
    {
        float sv = 0.f;
#pragma unroll
        for (int w = 0; w < RSLOTS; ++w) sv += sRed[w * 256 + t];
        sP2[t] = sv;
    }
    __syncthreads();
    CLUSTER_SYNC();

    // rank 0 gathers, squashes, writes output
    if (rank == 0) {
        uint32_t myP2 = smem_u32(sP2 + t);
        float s2 = 0.f;
#pragma unroll
        for (uint32_t r = 0; r < CL; ++r) s2 += ld_dsmem(mapa_u32(myP2, r));
        s2 += bias;
        out[b * 256 + t] = squash_val(s2);
    }
    CLUSTER_SYNC();   // keep peer smem alive until rank 0 finishes reading
}

extern "C" void kernel_launch(void* const* d_in, const int* in_sizes, int n_in,
                              void* d_out, int out_size) {
    const float* x    = (const float*)d_in[0];   // [128,1152,8]
    const float* W    = (const float*)d_in[1];   // [16,1152,16,8]
    const float* Bias = (const float*)d_in[2];   // [16,16]
    float* out = (float*)d_out;                  // [128,16,16]

    cudaFuncSetAttribute(k_route, cudaFuncAttributeMaxDynamicSharedMemorySize,
                         RSMEM);

    k_hat<<<dim3(ICHUNKS, NB / BC), 256>>>(x, W);      // (72,8) = 576 CTAs
    k_route<<<dim3(CL, NB), 256, RSMEM>>>(Bias, out);  // 128 clusters of 4
}

// round 13
// speedup vs baseline: 1.5059x; 1.5059x over previous
#include <cuda_runtime.h>
#include <cuda_fp16.h>
#include <stdint.h>
#include <math.h>

#define NB 128
#define NI 1152
#define IC 16                   // i per k_hat CTA
#define ICHUNKS (NI/IC)         // 72
#define BC 16                   // b per k_hat CTA (8 pairs) — measured best
#define RW 24                   // k_route warps; one i per warp per step
#define RSTEPS (NI/RW)          // 48

// Scratch (static device globals; no runtime allocation)
__device__ __half g_hat[(size_t)NB * NI * 256];   // [b][i][n*16+e], 75.5 MB
__device__ float  g_s0p[(size_t)ICHUNKS * NB * 256];

// ---- packed f32x2 helpers (Blackwell FFMA2 via PTX) ----
__device__ __forceinline__ uint64_t pk(float a, float b) {
    uint64_t r; asm("mov.b64 %0, {%1,%2};" : "=l"(r) : "f"(a), "f"(b)); return r;
}
__device__ __forceinline__ void unpk(uint64_t v, float& lo, float& hi) {
    asm("mov.b64 {%0,%1}, %2;" : "=f"(lo), "=f"(hi) : "l"(v));
}
__device__ __forceinline__ uint64_t mul2(uint64_t a, uint64_t b) {
    uint64_t r; asm("mul.rn.f32x2 %0, %1, %2;" : "=l"(r) : "l"(a), "l"(b)); return r;
}
__device__ __forceinline__ void fma2(uint64_t& d, uint64_t a, uint64_t b) {
    asm("fma.rn.f32x2 %0, %1, %2, %3;" : "=l"(d) : "l"(a), "l"(b), "l"(d));
}
__device__ __forceinline__ void add2(uint64_t& d, uint64_t a) {
    asm("add.rn.f32x2 %0, %1, %2;" : "=l"(d) : "l"(a), "l"(d));
}

// ---------------------------------------------------------------------------
// k_hat (R8-measured-best, byte-exact): hat[b,i,n,e] = sum_d x[b,i,d]*W[n,i,e,d]
// grid (72, 8), 256 threads: t = n*16 + e. Batch pairs via packed f32x2,
// manual W double-buffer, LDS.128 x reads. Emits iter-0 partials.
// ---------------------------------------------------------------------------
__global__ void __launch_bounds__(256) k_hat(const float* __restrict__ x,
                                             const float* __restrict__ W) {
    __shared__ uint64_t sxp[8][IC][8];   // (x_b, x_b+1) pairs, 8KB
    const int t  = threadIdx.x;
    const int i0 = blockIdx.x * IC;
    const int b0 = blockIdx.y * BC;

    for (int idx = t; idx < 8 * IC * 8; idx += 256) {
        int b2 = idx >> 7, rem = idx & 127;
        int ii = rem >> 3, d = rem & 7;
        float va = x[((size_t)(b0 + 2*b2    ) * NI + i0 + ii) * 8 + d];
        float vb = x[((size_t)(b0 + 2*b2 + 1) * NI + i0 + ii) * 8 + d];
        sxp[b2][ii][d] = pk(va, vb);
    }
    __syncthreads();

    const float4* wp = reinterpret_cast<const float4*>(W)
                     + ((size_t)((t >> 4) * NI + i0) * 16 + (t & 15)) * 2;

    uint64_t s0[8];
#pragma unroll
    for (int k = 0; k < 8; ++k) s0[k] = 0ull;

    float4 wa = wp[0], wb = wp[1];
    for (int i = 0; i < IC; ++i) {
        float4 na, nb;
        if (i + 1 < IC) { na = wp[32]; nb = wp[33]; }
        wp += 32;

        uint64_t ws[8];
        ws[0] = pk(wa.x, wa.x); ws[1] = pk(wa.y, wa.y);
        ws[2] = pk(wa.z, wa.z); ws[3] = pk(wa.w, wa.w);
        ws[4] = pk(wb.x, wb.x); ws[5] = pk(wb.y, wb.y);
        ws[6] = pk(wb.z, wb.z); ws[7] = pk(wb.w, wb.w);

#pragma unroll
        for (int b2 = 0; b2 < 8; ++b2) {
            const ulonglong2* xp2 = reinterpret_cast<const ulonglong2*>(&sxp[b2][i][0]);
            ulonglong2 q0 = xp2[0], q1 = xp2[1];
            ulonglong2 q2 = xp2[2], q3 = xp2[3];
            uint64_t acc = mul2(ws[0], q0.x);
            fma2(acc, ws[1], q0.y);
            fma2(acc, ws[2], q1.x);
            fma2(acc, ws[3], q1.y);
            fma2(acc, ws[4], q2.x);
            fma2(acc, ws[5], q2.y);
            fma2(acc, ws[6], q3.x);
            fma2(acc, ws[7], q3.y);
            add2(s0[b2], acc);
            float lo, hi; unpk(acc, lo, hi);
            size_t base = ((size_t)(b0 + 2*b2) * NI + i0 + i) * 256 + t;
            g_hat[base]                    = __float2half_rn(lo);
            g_hat[base + (size_t)NI * 256] = __float2half_rn(hi);
        }
        wa = na; wb = nb;
    }
#pragma unroll
    for (int b2 = 0; b2 < 8; ++b2) {
        float lo, hi; unpk(s0[b2], lo, hi);
        g_s0p[((size_t)blockIdx.x * NB + b0 + 2*b2    ) * 256 + t] = lo;
        g_s0p[((size_t)blockIdx.x * NB + b0 + 2*b2 + 1) * 256 + t] = hi;
    }
}

// squash along e via warp butterfly over low 4 lane bits (t = n*16+e)
__device__ __forceinline__ float squash_val(float sv) {
    float sq = sv * sv;
    sq += __shfl_xor_sync(0xffffffffu, sq, 1);
    sq += __shfl_xor_sync(0xffffffffu, sq, 2);
    sq += __shfl_xor_sync(0xffffffffu, sq, 4);
    sq += __shfl_xor_sync(0xffffffffu, sq, 8);
    float scale = sq / ((1.f + sq) * sqrtf(sq));
    return sv * scale;
}

// One i, COALESCED: the warp's single LDG.128 covers the full 512B i-row
// (lane l -> 16B chunk l). Thread owns (n = l>>1, e-half = l&1, 8 e's).
// dot: 4 fma2 + 1 shfl (combine e-halves); den: 4 shfl over n; acc: 4 fma2.
__device__ __forceinline__ void step_i(uint4 A, const uint64_t vecp[4],
                                       uint64_t sacc[4]) {
    uint64_t fp[4];
    const __half2* ha = reinterpret_cast<const __half2*>(&A);
#pragma unroll
    for (int j = 0; j < 4; ++j) { float2 v = __half22float2(ha[j]); fp[j] = pk(v.x, v.y); }

    uint64_t dacc = mul2(vecp[0], fp[0]);
    fma2(dacc, vecp[1], fp[1]);
    fma2(dacc, vecp[2], fp[2]);
    fma2(dacc, vecp[3], fp[3]);
    float dlo, dhi; unpk(dacc, dlo, dhi);
    float dh = dlo + dhi;
    float dot = dh + __shfl_xor_sync(0xffffffffu, dh, 1);   // combine e-halves
    float E = __expf(dot);
    float den = E;
    den += __shfl_xor_sync(0xffffffffu, den, 2);
    den += __shfl_xor_sync(0xffffffffu, den, 4);
    den += __shfl_xor_sync(0xffffffffu, den, 8);
    den += __shfl_xor_sync(0xffffffffu, den, 16);           // softmax over n
    float c = __fdividef(E, den);
    uint64_t cp = pk(c, c);
#pragma unroll
    for (int j = 0; j < 4; ++j) fma2(sacc[j], cp, fp[j]);
}

// One full sweep over all NI i's. Warp w handles i = w + RW*s; one LDG.128
// per i (fully coalesced: 4 wavefronts vs 16 for the strided layout).
// st = +S forward / -S reverse (L2 temporal locality on pass 2).
// 2-step unroll, 4 LDG.128 in flight per warp.
__device__ __forceinline__ void sweep(const uint4* p, int st,
                                      const uint64_t vecp[4],
                                      int n, int eh, int warp,
                                      float sRed[RW][256]) {
    uint64_t sacc[4];
#pragma unroll
    for (int j = 0; j < 4; ++j) sacc[j] = 0ull;

    uint4 A = p[0], B = p[st];
#pragma unroll 2
    for (int s = 0; s < RSTEPS; s += 2) {
        uint4 C, D;
        if (s + 2 < RSTEPS) { C = p[2*st]; D = p[3*st]; }
        p += 2 * st;
        step_i(A, vecp, sacc);
        step_i(B, vecp, sacc);
        A = C; B = D;
    }
    const int base = n * 16 + eh * 8;
#pragma unroll
    for (int j = 0; j < 4; ++j) {
        float lo, hi; unpk(sacc[j], lo, hi);
        sRed[warp][base + 2*j]     = lo;
        sRed[warp][base + 2*j + 1] = hi;
    }
}

// ---------------------------------------------------------------------------
// k_route: all routing in one kernel, one CTA per batch. grid 128, 768 thr.
// head(out0) -> pass1 (forward) -> out1 -> pass2 (reverse) -> squash -> out.
// ---------------------------------------------------------------------------
__global__ void __launch_bounds__(768) k_route(const float* __restrict__ Bias,
                                               float* __restrict__ out) {
    __shared__ float sVec[256];
    __shared__ float sOut0[256];
    __shared__ float sRed[RW][256];   // 24KB

    const int b = blockIdx.x, t = threadIdx.x;
    const int warp = t >> 5, lane = t & 31;
    const int n = lane >> 1, eh = lane & 1;

    // ---- head: out0 = squash(sum_i hat /16 + Bias) ----
    if (t < 256) {
        float sv = 0.f;
        for (int c = 0; c < ICHUNKS; ++c)
            sv += g_s0p[((size_t)c * NB + b) * 256 + t];
        sv = sv * (1.f / 16.f) + Bias[t];
        float o = squash_val(sv);
        sOut0[t] = o; sVec[t] = o;
    }
    __syncthreads();

    const int S = RW * 32;   // uint4 stride between this warp's consecutive i's
    const uint4* pF = reinterpret_cast<const uint4*>(g_hat)
                    + ((size_t)b * NI + warp) * 32 + lane;      // forward start
    const uint4* pR = pF + (size_t)(RSTEPS - 1) * S;            // reverse start

    uint64_t vecp[4];
#pragma unroll
    for (int j = 0; j < 4; ++j)
        vecp[j] = pk(sVec[n * 16 + eh * 8 + 2*j], sVec[n * 16 + eh * 8 + 2*j + 1]);

    // ---- pass 1: b1 = out0 . hat (forward) ----
    sweep(pF, S, vecp, n, eh, warp, sRed);
    __syncthreads();
    if (t < 256) {
        float sv = 0.f;
#pragma unroll
        for (int w = 0; w < RW; ++w) sv += sRed[w][t];
        sv += Bias[t];
        sVec[t] = sOut0[t] + squash_val(sv);   // telescoped vec = out0 + out1
    }
    __syncthreads();

#pragma unroll
    for (int j = 0; j < 4; ++j)
        vecp[j] = pk(sVec[n * 16 + eh * 8 + 2*j], sVec[n * 16 + eh * 8 + 2*j + 1]);

    // ---- pass 2: b2 = (out0+out1) . hat (reverse), final squash ----
    sweep(pR, -S, vecp, n, eh, warp, sRed);
    __syncthreads();
    if (t < 256) {
        float sv = 0.f;
#pragma unroll
        for (int w = 0; w < RW; ++w) sv += sRed[w][t];
        sv += Bias[t];
        out[b * 256 + t] = squash_val(sv);
    }
}

extern "C" void kernel_launch(void* const* d_in, const int* in_sizes, int n_in,
                              void* d_out, int out_size) {
    const float* x    = (const float*)d_in[0];   // [128,1152,8]
    const float* W    = (const float*)d_in[1];   // [16,1152,16,8]
    const float* Bias = (const float*)d_in[2];   // [16,16]
    float* out = (float*)d_out;                  // [128,16,16]

    k_hat<<<dim3(ICHUNKS, NB / BC), 256>>>(x, W);   // (72,8) = 576 CTAs
    k_route<<<NB, 768>>>(Bias, out);                // 128 CTAs, 1 per batch
}

// round 14
// speedup vs baseline: 1.5115x; 1.0038x over previous
#include <cuda_runtime.h>
#include <cuda_fp16.h>
#include <stdint.h>
#include <math.h>

#define NB 128
#define NI 1152
#define IC 16                   // i per k_hat CTA
#define ICHUNKS (NI/IC)         // 72
#define BC 16                   // b per k_hat CTA (8 pairs) — measured best
#define RW 24                   // k_route warps; one i per warp per step
#define RSTEPS (NI/RW)          // 48 (divisible by 4 for the 4-step unroll)

// Scratch (static device globals; no runtime allocation)
__device__ __half g_hat[(size_t)NB * NI * 256];   // [b][i][n*16+e], 75.5 MB
__device__ float  g_s0p[(size_t)ICHUNKS * NB * 256];

// ---- packed f32x2 helpers (Blackwell FFMA2 via PTX) ----
__device__ __forceinline__ uint64_t pk(float a, float b) {
    uint64_t r; asm("mov.b64 %0, {%1,%2};" : "=l"(r) : "f"(a), "f"(b)); return r;
}
__device__ __forceinline__ void unpk(uint64_t v, float& lo, float& hi) {
    asm("mov.b64 {%0,%1}, %2;" : "=f"(lo), "=f"(hi) : "l"(v));
}
__device__ __forceinline__ uint64_t mul2(uint64_t a, uint64_t b) {
    uint64_t r; asm("mul.rn.f32x2 %0, %1, %2;" : "=l"(r) : "l"(a), "l"(b)); return r;
}
__device__ __forceinline__ void fma2(uint64_t& d, uint64_t a, uint64_t b) {
    asm("fma.rn.f32x2 %0, %1, %2, %3;" : "=l"(d) : "l"(a), "l"(b), "l"(d));
}
__device__ __forceinline__ void add2(uint64_t& d, uint64_t a) {
    asm("add.rn.f32x2 %0, %1, %2;" : "=l"(d) : "l"(a), "l"(d));
}

// ---------------------------------------------------------------------------
// k_hat (R8-measured-best, byte-exact): hat[b,i,n,e] = sum_d x[b,i,d]*W[n,i,e,d]
// grid (72, 8), 256 threads: t = n*16 + e. Batch pairs via packed f32x2,
// manual W double-buffer, LDS.128 x reads. Emits iter-0 partials.
// ---------------------------------------------------------------------------
__global__ void __launch_bounds__(256) k_hat(const float* __restrict__ x,
                                             const float* __restrict__ W) {
    __shared__ uint64_t sxp[8][IC][8];   // (x_b, x_b+1) pairs, 8KB
    const int t  = threadIdx.x;
    const int i0 = blockIdx.x * IC;
    const int b0 = blockIdx.y * BC;

    for (int idx = t; idx < 8 * IC * 8; idx += 256) {
        int b2 = idx >> 7, rem = idx & 127;
        int ii = rem >> 3, d = rem & 7;
        float va = x[((size_t)(b0 + 2*b2    ) * NI + i0 + ii) * 8 + d];
        float vb = x[((size_t)(b0 + 2*b2 + 1) * NI + i0 + ii) * 8 + d];
        sxp[b2][ii][d] = pk(va, vb);
    }
    __syncthreads();

    const float4* wp = reinterpret_cast<const float4*>(W)
                     + ((size_t)((t >> 4) * NI + i0) * 16 + (t & 15)) * 2;

    uint64_t s0[8];
#pragma unroll
    for (int k = 0; k < 8; ++k) s0[k] = 0ull;

    float4 wa = wp[0], wb = wp[1];
    for (int i = 0; i < IC; ++i) {
        float4 na, nb;
        if (i + 1 < IC) { na = wp[32]; nb = wp[33]; }
        wp += 32;

        uint64_t ws[8];
        ws[0] = pk(wa.x, wa.x); ws[1] = pk(wa.y, wa.y);
        ws[2] = pk(wa.z, wa.z); ws[3] = pk(wa.w, wa.w);
        ws[4] = pk(wb.x, wb.x); ws[5] = pk(wb.y, wb.y);
        ws[6] = pk(wb.z, wb.z); ws[7] = pk(wb.w, wb.w);

#pragma unroll
        for (int b2 = 0; b2 < 8; ++b2) {
            const ulonglong2* xp2 = reinterpret_cast<const ulonglong2*>(&sxp[b2][i][0]);
            ulonglong2 q0 = xp2[0], q1 = xp2[1];
            ulonglong2 q2 = xp2[2], q3 = xp2[3];
            uint64_t acc = mul2(ws[0], q0.x);
            fma2(acc, ws[1], q0.y);
            fma2(acc, ws[2], q1.x);
            fma2(acc, ws[3], q1.y);
            fma2(acc, ws[4], q2.x);
            fma2(acc, ws[5], q2.y);
            fma2(acc, ws[6], q3.x);
            fma2(acc, ws[7], q3.y);
            add2(s0[b2], acc);
            float lo, hi; unpk(acc, lo, hi);
            size_t base = ((size_t)(b0 + 2*b2) * NI + i0 + i) * 256 + t;
            g_hat[base]                    = __float2half_rn(lo);
            g_hat[base + (size_t)NI * 256] = __float2half_rn(hi);
        }
        wa = na; wb = nb;
    }
#pragma unroll
    for (int b2 = 0; b2 < 8; ++b2) {
        float lo, hi; unpk(s0[b2], lo, hi);
        g_s0p[((size_t)blockIdx.x * NB + b0 + 2*b2    ) * 256 + t] = lo;
        g_s0p[((size_t)blockIdx.x * NB + b0 + 2*b2 + 1) * 256 + t] = hi;
    }
}

// squash along e via warp butterfly over low 4 lane bits (t = n*16+e)
__device__ __forceinline__ float squash_val(float sv) {
    float sq = sv * sv;
    sq += __shfl_xor_sync(0xffffffffu, sq, 1);
    sq += __shfl_xor_sync(0xffffffffu, sq, 2);
    sq += __shfl_xor_sync(0xffffffffu, sq, 4);
    sq += __shfl_xor_sync(0xffffffffu, sq, 8);
    float scale = sq / ((1.f + sq) * sqrtf(sq));
    return sv * scale;
}

// One i, COALESCED: the warp's single LDG.128 covers the full 512B i-row
// (lane l -> 16B chunk l). Thread owns (n = l>>1, e-half = l&1, 8 e's).
__device__ __forceinline__ void step_i(uint4 A, const uint64_t vecp[4],
                                       uint64_t sacc[4]) {
    uint64_t fp[4];
    const __half2* ha = reinterpret_cast<const __half2*>(&A);
#pragma unroll
    for (int j = 0; j < 4; ++j) { float2 v = __half22float2(ha[j]); fp[j] = pk(v.x, v.y); }

    uint64_t dacc = mul2(vecp[0], fp[0]);
    fma2(dacc, vecp[1], fp[1]);
    fma2(dacc, vecp[2], fp[2]);
    fma2(dacc, vecp[3], fp[3]);
    float dlo, dhi; unpk(dacc, dlo, dhi);
    float dh = dlo + dhi;
    float dot = dh + __shfl_xor_sync(0xffffffffu, dh, 1);   // combine e-halves
    float E = __expf(dot);
    float den = E;
    den += __shfl_xor_sync(0xffffffffu, den, 2);
    den += __shfl_xor_sync(0xffffffffu, den, 4);
    den += __shfl_xor_sync(0xffffffffu, den, 8);
    den += __shfl_xor_sync(0xffffffffu, den, 16);           // softmax over n
    float c = __fdividef(E, den);
    uint64_t cp = pk(c, c);
#pragma unroll
    for (int j = 0; j < 4; ++j) fma2(sacc[j], cp, fp[j]);
}

// One full sweep over all NI i's. Warp w handles i = w + RW*s; one coalesced
// LDG.128 per i. 4-step unroll -> 4 LDG.128 in flight per warp (R9's MLP at
// R13's wavefront count). st = +S forward / -S reverse.
__device__ __forceinline__ void sweep(const uint4* p, int st,
                                      const uint64_t vecp[4],
                                      int n, int eh, int warp,
                                      float sRed[RW][256]) {
    uint64_t sacc[4];
#pragma unroll
    for (int j = 0; j < 4; ++j) sacc[j] = 0ull;

    uint4 A = p[0], B = p[st], C = p[2*st], D = p[3*st];
#pragma unroll
    for (int s = 0; s < RSTEPS; s += 4) {
        uint4 E, F, G, H;
        if (s + 4 < RSTEPS) {        // RSTEPS%4==0: all-or-none per group
            E = p[4*st]; F = p[5*st]; G = p[6*st]; H = p[7*st];
        }
        p += 4 * st;
        step_i(A, vecp, sacc);
        step_i(B, vecp, sacc);
        step_i(C, vecp, sacc);
        step_i(D, vecp, sacc);
        A = E; B = F; C = G; D = H;
    }
    const int base = n * 16 + eh * 8;
#pragma unroll
    for (int j = 0; j < 4; ++j) {
        float lo, hi; unpk(sacc[j], lo, hi);
        sRed[warp][base + 2*j]     = lo;
        sRed[warp][base + 2*j + 1] = hi;
    }
}

// ---------------------------------------------------------------------------
// k_route: all routing in one kernel, one CTA per batch. grid 128, 768 thr.
// head(out0) -> pass1 (forward) -> out1 -> pass2 (reverse) -> squash -> out.
// ---------------------------------------------------------------------------
__global__ void __launch_bounds__(768) k_route(const float* __restrict__ Bias,
                                               float* __restrict__ out) {
    __shared__ float sVec[256];
    __shared__ float sOut0[256];
    __shared__ float sRed[RW][256];   // 24KB

    const int b = blockIdx.x, t = threadIdx.x;
    const int warp = t >> 5, lane = t & 31;
    const int n = lane >> 1, eh = lane & 1;

    // ---- head: out0 = squash(sum_i hat /16 + Bias) ----
    if (t < 256) {
        float sv = 0.f;
        for (int c = 0; c < ICHUNKS; ++c)
            sv += g_s0p[((size_t)c * NB + b) * 256 + t];
        sv = sv * (1.f / 16.f) + Bias[t];
        float o = squash_val(sv);
        sOut0[t] = o; sVec[t] = o;
    }
    __syncthreads();

    const int S = RW * 32;   // uint4 stride between this warp's consecutive i's
    const uint4* pF = reinterpret_cast<const uint4*>(g_hat)
                    + ((size_t)b * NI + warp) * 32 + lane;      // forward start
    const uint4* pR = pF + (size_t)(RSTEPS - 1) * S;            // reverse start

    uint64_t vecp[4];
#pragma unroll
    for (int j = 0; j < 4; ++j)
        vecp[j] = pk(sVec[n * 16 + eh * 8 + 2*j], sVec[n * 16 + eh * 8 + 2*j + 1]);

    // ---- pass 1: b1 = out0 . hat (forward) ----
    sweep(pF, S, vecp, n, eh, warp, sRed);
    __syncthreads();
    if (t < 256) {
        float sv = 0.f;
#pragma unroll
        for (int w = 0; w < RW; ++w) sv += sRed[w][t];
        sv += Bias[t];
        sVec[t] = sOut0[t] + squash_val(sv);   // telescoped vec = out0 + out1
    }
    __syncthreads();

#pragma unroll
    for (int j = 0; j < 4; ++j)
        vecp[j] = pk(sVec[n * 16 + eh * 8 + 2*j], sVec[n * 16 + eh * 8 + 2*j + 1]);

    // ---- pass 2: b2 = (out0+out1) . hat (reverse), final squash ----
    sweep(pR, -S, vecp, n, eh, warp, sRed);
    __syncthreads();
    if (t < 256) {
        float sv = 0.f;
#pragma unroll
        for (int w = 0; w < RW; ++w) sv += sRed[w][t];
        sv += Bias[t];
        out[b * 256 + t] = squash_val(sv);
    }
}

extern "C" void kernel_launch(void* const* d_in, const int* in_sizes, int n_in,
                              void* d_out, int out_size) {
    const float* x    = (const float*)d_in[0];   // [128,1152,8]
    const float* W    = (const float*)d_in[1];   // [16,1152,16,8]
    const float* Bias = (const float*)d_in[2];   // [16,16]
    float* out = (float*)d_out;                  // [128,16,16]

    k_hat<<<dim3(ICHUNKS, NB / BC), 256>>>(x, W);   // (72,8) = 576 CTAs
    k_route<<<NB, 768>>>(Bias, out);                // 128 CTAs, 1 per batch
}

// round 15
// speedup vs baseline: 1.6547x; 1.0947x over previous
#include <cuda_runtime.h>
#include <cuda_fp16.h>
#include <stdint.h>
#include <math.h>

#define NB 128
#define NI 1152
#define IC 16                   // i per k_hat CTA
#define ICHUNKS (NI/IC)         // 72
#define BC 16                   // b per k_hat CTA (8 pairs) — measured best
#define SLOTS 48                // i-slots in k_route (24 warps x 2)
#define STEPS (NI/SLOTS)        // 24

// Scratch (static device globals; no runtime allocation)
__device__ __half g_hat[(size_t)NB * NI * 256];   // [b][i][n*16+e], 75.5 MB
__device__ float  g_s0p[(size_t)ICHUNKS * NB * 256];

// ---- packed f32x2 helpers (Blackwell FFMA2 via PTX) ----
__device__ __forceinline__ uint64_t pk(float a, float b) {
    uint64_t r; asm("mov.b64 %0, {%1,%2};" : "=l"(r) : "f"(a), "f"(b)); return r;
}
__device__ __forceinline__ void unpk(uint64_t v, float& lo, float& hi) {
    asm("mov.b64 {%0,%1}, %2;" : "=f"(lo), "=f"(hi) : "l"(v));
}
__device__ __forceinline__ uint64_t mul2(uint64_t a, uint64_t b) {
    uint64_t r; asm("mul.rn.f32x2 %0, %1, %2;" : "=l"(r) : "l"(a), "l"(b)); return r;
}
__device__ __forceinline__ void fma2(uint64_t& d, uint64_t a, uint64_t b) {
    asm("fma.rn.f32x2 %0, %1, %2, %3;" : "=l"(d) : "l"(a), "l"(b), "l"(d));
}
__device__ __forceinline__ void add2(uint64_t& d, uint64_t a) {
    asm("add.rn.f32x2 %0, %1, %2;" : "=l"(d) : "l"(a), "l"(d));
}

// ---------------------------------------------------------------------------
// k_hat (R8-measured-best, byte-exact): hat[b,i,n,e] = sum_d x[b,i,d]*W[n,i,e,d]
// grid (72, 8), 256 threads: t = n*16 + e. Batch pairs via packed f32x2,
// manual W double-buffer, LDS.128 x reads. Emits iter-0 partials.
// ---------------------------------------------------------------------------
__global__ void __launch_bounds__(256) k_hat(const float* __restrict__ x,
                                             const float* __restrict__ W) {
    __shared__ uint64_t sxp[8][IC][8];   // (x_b, x_b+1) pairs, 8KB
    const int t  = threadIdx.x;
    const int i0 = blockIdx.x * IC;
    const int b0 = blockIdx.y * BC;

    for (int idx = t; idx < 8 * IC * 8; idx += 256) {
        int b2 = idx >> 7, rem = idx & 127;
        int ii = rem >> 3, d = rem & 7;
        float va = x[((size_t)(b0 + 2*b2    ) * NI + i0 + ii) * 8 + d];
        float vb = x[((size_t)(b0 + 2*b2 + 1) * NI + i0 + ii) * 8 + d];
        sxp[b2][ii][d] = pk(va, vb);
    }
    __syncthreads();

    const float4* wp = reinterpret_cast<const float4*>(W)
                     + ((size_t)((t >> 4) * NI + i0) * 16 + (t & 15)) * 2;

    uint64_t s0[8];
#pragma unroll
    for (int k = 0; k < 8; ++k) s0[k] = 0ull;

    float4 wa = wp[0], wb = wp[1];
    for (int i = 0; i < IC; ++i) {
        float4 na, nb;
        if (i + 1 < IC) { na = wp[32]; nb = wp[33]; }
        wp += 32;

        uint64_t ws[8];
        ws[0] = pk(wa.x, wa.x); ws[1] = pk(wa.y, wa.y);
        ws[2] = pk(wa.z, wa.z); ws[3] = pk(wa.w, wa.w);
        ws[4] = pk(wb.x, wb.x); ws[5] = pk(wb.y, wb.y);
        ws[6] = pk(wb.z, wb.z); ws[7] = pk(wb.w, wb.w);

#pragma unroll
        for (int b2 = 0; b2 < 8; ++b2) {
            const ulonglong2* xp2 = reinterpret_cast<const ulonglong2*>(&sxp[b2][i][0]);
            ulonglong2 q0 = xp2[0], q1 = xp2[1];
            ulonglong2 q2 = xp2[2], q3 = xp2[3];
            uint64_t acc = mul2(ws[0], q0.x);
            fma2(acc, ws[1], q0.y);
            fma2(acc, ws[2], q1.x);
            fma2(acc, ws[3], q1.y);
            fma2(acc, ws[4], q2.x);
            fma2(acc, ws[5], q2.y);
            fma2(acc, ws[6], q3.x);
            fma2(acc, ws[7], q3.y);
            add2(s0[b2], acc);
            float lo, hi; unpk(acc, lo, hi);
            size_t base = ((size_t)(b0 + 2*b2) * NI + i0 + i) * 256 + t;
            g_hat[base]                    = __float2half_rn(lo);
            g_hat[base + (size_t)NI * 256] = __float2half_rn(hi);
        }
        wa = na; wb = nb;
    }
#pragma unroll
    for (int b2 = 0; b2 < 8; ++b2) {
        float lo, hi; unpk(s0[b2], lo, hi);
        g_s0p[((size_t)blockIdx.x * NB + b0 + 2*b2    ) * 256 + t] = lo;
        g_s0p[((size_t)blockIdx.x * NB + b0 + 2*b2 + 1) * 256 + t] = hi;
    }
}

// squash along e via warp butterfly over low 4 lane bits (t = n*16+e)
__device__ __forceinline__ float squash_val(float sv) {
    float sq = sv * sv;
    sq += __shfl_xor_sync(0xffffffffu, sq, 1);
    sq += __shfl_xor_sync(0xffffffffu, sq, 2);
    sq += __shfl_xor_sync(0xffffffffu, sq, 4);
    sq += __shfl_xor_sync(0xffffffffu, sq, 8);
    float scale = sq / ((1.f + sq) * sqrtf(sq));
    return sv * scale;
}

// One i: fp16 hat fragment (16 e for this thread's n) -> logit dot (packed),
// softmax over n (4 shfl), packed-fma accumulate into sacc.  [R9-exact]
__device__ __forceinline__ void step_i(uint4 A0, uint4 A1,
                                       const uint64_t vecp[8], uint64_t sacc[8]) {
    uint64_t fp[8];
    const __half2* ha = reinterpret_cast<const __half2*>(&A0);
#pragma unroll
    for (int j = 0; j < 4; ++j) { float2 v = __half22float2(ha[j]); fp[j] = pk(v.x, v.y); }
    const __half2* hb = reinterpret_cast<const __half2*>(&A1);
#pragma unroll
    for (int j = 0; j < 4; ++j) { float2 v = __half22float2(hb[j]); fp[4+j] = pk(v.x, v.y); }

    uint64_t dacc = mul2(vecp[0], fp[0]);
#pragma unroll
    for (int j = 1; j < 8; ++j) fma2(dacc, vecp[j], fp[j]);
    float dlo, dhi; unpk(dacc, dlo, dhi);
    float E = __expf(dlo + dhi);
    float den = E;
    den += __shfl_xor_sync(0xffffffffu, den, 1);
    den += __shfl_xor_sync(0xffffffffu, den, 2);
    den += __shfl_xor_sync(0xffffffffu, den, 4);
    den += __shfl_xor_sync(0xffffffffu, den, 8);
    float c = __fdividef(E, den);
    uint64_t cp = pk(c, c);
#pragma unroll
    for (int j = 0; j < 8; ++j) fma2(sacc[j], cp, fp[j]);
}

// One full sweep over all NI i's (R9-exact). st = +S forward / -S reverse.
// 2-step unroll, 4 LDG.128 in flight per lane.
__device__ __forceinline__ void sweep(const uint4* p, int st,
                                      const uint64_t vecp[8],
                                      int n, int slot, float sRed[SLOTS][256]) {
    uint64_t sacc[8];
#pragma unroll
    for (int j = 0; j < 8; ++j) sacc[j] = 0ull;

    uint4 A0 = p[0], A1 = p[1], B0 = p[st], B1 = p[st + 1];
#pragma unroll 2
    for (int s = 0; s < STEPS; s += 2) {
        uint4 C0, C1, D0, D1;
        if (s + 2 < STEPS) {
            C0 = p[2*st]; C1 = p[2*st + 1];
            D0 = p[3*st]; D1 = p[3*st + 1];
        }
        p += 2 * st;
        step_i(A0, A1, vecp, sacc);
        step_i(B0, B1, vecp, sacc);
        A0 = C0; A1 = C1; B0 = D0; B1 = D1;
    }
#pragma unroll
    for (int j = 0; j < 8; ++j) {
        float lo, hi; unpk(sacc[j], lo, hi);
        sRed[slot][n * 16 + 2*j]     = lo;
        sRed[slot][n * 16 + 2*j + 1] = hi;
    }
}

// ---------------------------------------------------------------------------
// k_route (R9-exact sweeps): one CTA per batch, grid 128, 768 threads.
// head(out0; 3-way parallelized) -> pass1 fwd -> out1 -> pass2 rev -> out.
// ---------------------------------------------------------------------------
__global__ void __launch_bounds__(768) k_route(const float* __restrict__ Bias,
                                               float* __restrict__ out) {
    __shared__ float sVec[256];
    __shared__ float sOut0[256];
    __shared__ float sGrp[3][256];
    __shared__ float sRed[SLOTS][256];   // 48KB

    const int b = blockIdx.x, t = threadIdx.x;
    const int warp = t >> 5, lane = t & 31;
    const int n = lane & 15, islot = lane >> 4;
    const int slot = warp * 2 + islot;

    // ---- head: out0 = squash(sum_i hat /16 + Bias); 72 chunks over 3 groups
    {
        const int g = t >> 8, tt = t & 255;
        float sv = 0.f;
#pragma unroll
        for (int c = g * 24; c < g * 24 + 24; ++c)
            sv += g_s0p[((size_t)c * NB + b) * 256 + tt];
        sGrp[g][tt] = sv;
    }
    __syncthreads();
    if (t < 256) {
        float sv = sGrp[0][t] + sGrp[1][t] + sGrp[2][t];
        sv = sv * (1.f / 16.f) + Bias[t];
        float o = squash_val(sv);
        sOut0[t] = o; sVec[t] = o;
    }
    __syncthreads();

    const int S = SLOTS * 32;
    const uint4* pF = reinterpret_cast<const uint4*>(g_hat)
                    + ((size_t)b * NI + slot) * 32 + n * 2;     // forward start
    const uint4* pR = pF + (size_t)(STEPS - 1) * S;             // reverse start

    uint64_t vecp[8];
#pragma unroll
    for (int j = 0; j < 8; ++j)
        vecp[j] = pk(sVec[n * 16 + 2*j], sVec[n * 16 + 2*j + 1]);

    // ---- pass 1: b1 = out0 . hat (forward) ----
    sweep(pF, S, vecp, n, slot, sRed);
    __syncthreads();
    if (t < 256) {
        float sv = 0.f;
#pragma unroll
        for (int w = 0; w < SLOTS; ++w) sv += sRed[w][t];
        sv += Bias[t];
        sVec[t] = sOut0[t] + squash_val(sv);   // telescoped vec = out0 + out1
    }
    __syncthreads();

#pragma unroll
    for (int j = 0; j < 8; ++j)
        vecp[j] = pk(sVec[n * 16 + 2*j], sVec[n * 16 + 2*j + 1]);

    // ---- pass 2: b2 = (out0+out1) . hat (reverse), final squash ----
    sweep(pR, -S, vecp, n, slot, sRed);
    __syncthreads();
    if (t < 256) {
        float sv = 0.f;
#pragma unroll
        for (int w = 0; w < SLOTS; ++w) sv += sRed[w][t];
        sv += Bias[t];
        out[b * 256 + t] = squash_val(sv);
    }
}

extern "C" void kernel_launch(void* const* d_in, const int* in_sizes, int n_in,
                              void* d_out, int out_size) {
    const float* x    = (const float*)d_in[0];   // [128,1152,8]
    const float* W    = (const float*)d_in[1];   // [16,1152,16,8]
    const float* Bias = (const float*)d_in[2];   // [16,16]
    float* out = (float*)d_out;                  // [128,16,16]

    k_hat<<<dim3(ICHUNKS, NB / BC), 256>>>(x, W);   // (72,8) = 576 CTAs
    k_route<<<NB, 768>>>(Bias, out);                // 128 CTAs, 1 per batch
}